// round 8
// baseline (speedup 1.0000x reference)
#include <cuda_runtime.h>
#include <cstdint>

// Problem constants (fixed by the reference config)
#define DM 8       // d_model
#define TT 33      // seq_len
#define FFD 28     // d_ff
#define RR 3       // ffn_rank
#define NMODELS 8
#define NBATCH 4096

#define NSEQ 32                          // sequences per block = lanes per warp
#define NTHREADS 512                     // 16 warps; warp w -> tokens w, w+16 (+32 for w=0)
#define BLOCKS_PER_MODEL (NBATCH / NSEQ)    // 128
#define NBLOCKS (NMODELS * BLOCKS_PER_MODEL) // 1024

// Per-sequence KV row: 33 tokens * 16 floats + 4 pad = 532 floats.
// 532 mod 32 = 20; within each 8-lane LDS.128 phase, (s mod 8)*20 mod 32 =
// {0,20,8,28,16,4,24,12} -> distinct bank quads; +8 lanes shifts by 160 ≡ 0
// mod 32, so every phase is conflict-free for s = 0..31.
#define KVSTRIDE (TT*16 + 4)
#define KVBYTES (NSEQ * KVSTRIDE * 4)    // 68096 bytes (dynamic smem)

typedef unsigned long long u64;

// ---- TF32 rounding (matches reference's TF32 tensor-core einsums) ----
__device__ __forceinline__ float tf32r(float x) {
    uint32_t y;
    asm("cvt.rna.tf32.f32 %0, %1;" : "=r"(y) : "f"(x));
    return __uint_as_float(y);
}

// ---- packed f32x2 ops (sm_100+) ----
__device__ __forceinline__ u64 pk2(float lo, float hi) {
    u64 r; asm("mov.b64 %0, {%1, %2};" : "=l"(r) : "f"(lo), "f"(hi)); return r;
}
__device__ __forceinline__ void upk2(u64 v, float& lo, float& hi) {
    asm("mov.b64 {%0, %1}, %2;" : "=f"(lo), "=f"(hi) : "l"(v));
}
__device__ __forceinline__ u64 fma2(u64 a, u64 b, u64 c) {
    u64 d; asm("fma.rn.f32x2 %0, %1, %2, %3;" : "=l"(d) : "l"(a), "l"(b), "l"(c)); return d;
}
__device__ __forceinline__ u64 mul2(u64 a, u64 b) {
    u64 d; asm("mul.rn.f32x2 %0, %1, %2;" : "=l"(d) : "l"(a), "l"(b)); return d;
}

__device__ __forceinline__ float dot8p(const u64* a, const float* w) {
    const ulonglong2* W = (const ulonglong2*)w;
    ulonglong2 w01 = W[0], w23 = W[1];
    u64 acc = mul2(a[0], w01.x);
    acc = fma2(a[1], w01.y, acc);
    acc = fma2(a[2], w23.x, acc);
    acc = fma2(a[3], w23.y, acc);
    float lo, hi; upk2(acc, lo, hi);
    return lo + hi;
}

// LN (exact fp32) -> TF32 quantize -> packed
__device__ __forceinline__ void ln_pack(const float* x, const float* lw, const float* lb, u64* outp) {
    float mean = 0.f;
    #pragma unroll
    for (int i = 0; i < 8; i++) mean += x[i];
    mean *= 0.125f;
    float var = 0.f;
    #pragma unroll
    for (int i = 0; i < 8; i++) { float d = x[i] - mean; var += d*d; }
    var *= 0.125f;
    float rstd = rsqrtf(var + 1e-5f);
    float h[8];
    #pragma unroll
    for (int i = 0; i < 8; i++) h[i] = tf32r((x[i] - mean) * rstd * lw[i] + lb[i]);
    #pragma unroll
    for (int i = 0; i < 4; i++) outp[i] = pk2(h[2*i], h[2*i+1]);
}

__global__ __launch_bounds__(NTHREADS, 2)
void block_fused_kernel(
    const float* __restrict__ gx,
    const float* __restrict__ gln1w, const float* __restrict__ gln1b,
    const float* __restrict__ gqkv,  const float* __restrict__ gproj,
    const float* __restrict__ gln2w, const float* __restrict__ gln2b,
    const float* __restrict__ gf1A,  const float* __restrict__ gf1B,
    const float* __restrict__ gf1W,  const float* __restrict__ gf2A,
    const float* __restrict__ gf2B,  const float* __restrict__ gf2W,
    float* __restrict__ gout)
{
    __shared__ __align__(16) float s_qkvT[3*DM][DM];   // [o][i]
    __shared__ __align__(16) float s_projT[DM][DM];    // [o][i]
    __shared__ __align__(16) float s_W1c[FFD][DM];     // [f][i] = f1Wf + f1A@f1B
    __shared__ __align__(16) float s_W2c[FFD][DM];     // [f][d] = f2Wf + f2A@f2B
    __shared__ __align__(16) float s_ln[4][DM];
    extern __shared__ __align__(16) float s_kv[];      // [NSEQ][KVSTRIDE], K(8)|V(8) per token

    const int tid = threadIdx.x;
    const int m  = blockIdx.x / BLOCKS_PER_MODEL;
    const int b0 = (blockIdx.x % BLOCKS_PER_MODEL) * NSEQ;

    // ---- stage weights (TF32-rounded; transposed; low-rank folded) ----
    for (int idx = tid; idx < 3*DM*DM; idx += NTHREADS) {
        int o = idx / DM, i = idx % DM;
        s_qkvT[o][i] = tf32r(gqkv[((long)m*DM + i)*(3*DM) + o]);
    }
    for (int idx = tid; idx < DM*DM; idx += NTHREADS) {
        int o = idx / DM, i = idx % DM;
        s_projT[o][i] = tf32r(gproj[((long)m*DM + i)*DM + o]);
    }
    for (int idx = tid; idx < FFD*DM; idx += NTHREADS) {
        int f = idx / DM, i = idx % DM;
        float acc = gf1W[((long)m*DM + i)*FFD + f];
        #pragma unroll
        for (int r = 0; r < RR; r++)
            acc = fmaf(gf1A[((long)m*DM + i)*RR + r],
                       gf1B[((long)m*RR + r)*FFD + f], acc);
        s_W1c[f][i] = tf32r(acc);
    }
    for (int idx = tid; idx < FFD*DM; idx += NTHREADS) {
        int f = idx / DM, d = idx % DM;
        float acc = gf2W[((long)m*FFD + f)*DM + d];
        #pragma unroll
        for (int r = 0; r < RR; r++)
            acc = fmaf(gf2A[((long)m*FFD + f)*RR + r],
                       gf2B[((long)m*RR + r)*DM + d], acc);
        s_W2c[f][d] = tf32r(acc);
    }
    for (int idx = tid; idx < 4*DM; idx += NTHREADS) {
        int which = idx / DM, i = idx % DM;
        const float* src = (which == 0) ? gln1w : (which == 1) ? gln1b
                         : (which == 2) ? gln2w : gln2b;
        s_ln[which][i] = src[(long)m*DM + i];
    }
    __syncthreads();

    // ---- warp-uniform mapping: lane = sequence, warp = token ----
    const int w = tid >> 5;    // warp 0..15
    const int s = tid & 31;    // sequence 0..31
    const long seqbase = (((long)m*NBATCH + b0 + s)*TT) * DM;
    const float qscale = 0.3535533905932738f;  // 1/sqrt(8)

    // ================= Phase A: QKV for tokens w and w+16 =================
    float xr[2][8];
    u64 qp[2][4];
    #pragma unroll
    for (int k = 0; k < 2; k++) {
        const int t = w + 16*k;
        const long base = seqbase + (long)t * DM;
        float4 a0 = *(const float4*)(gx + base);
        float4 a1 = *(const float4*)(gx + base + 4);
        xr[k][0]=a0.x; xr[k][1]=a0.y; xr[k][2]=a0.z; xr[k][3]=a0.w;
        xr[k][4]=a1.x; xr[k][5]=a1.y; xr[k][6]=a1.z; xr[k][7]=a1.w;

        u64 hp[4];
        ln_pack(xr[k], s_ln[0], s_ln[1], hp);

        float q[8];
        #pragma unroll
        for (int o = 0; o < 8; o++) q[o] = tf32r(dot8p(hp, s_qkvT[o])) * qscale;
        #pragma unroll
        for (int i = 0; i < 4; i++) qp[k][i] = pk2(q[2*i], q[2*i+1]);

        float kvv[16];
        #pragma unroll
        for (int o = 0; o < 16; o++) kvv[o] = tf32r(dot8p(hp, s_qkvT[8 + o]));
        float* dst = s_kv + s*KVSTRIDE + t*16;
        #pragma unroll
        for (int i = 0; i < 4; i++)
            ((float4*)dst)[i] = make_float4(kvv[4*i], kvv[4*i+1], kvv[4*i+2], kvv[4*i+3]);
    }
    __syncthreads();

    // ============ Phase B: attention + proj + LN2 + MLP per token ============
    #pragma unroll
    for (int k = 0; k < 2; k++) {
        const int t = w + 16*k;
        const long base = seqbase + (long)t * DM;

        // single-pass causal attention (scores tiny => no max subtraction)
        u64 a01 = 0, a23 = 0, a45 = 0, a67 = 0;
        float l = 0.f;
        const float* kvp = s_kv + s*KVSTRIDE;
        for (int j = 0; j <= t; j++) {
            const ulonglong2* kj = (const ulonglong2*)(kvp + j*16);
            ulonglong2 k01 = kj[0], k23 = kj[1];
            u64 d2 = mul2(qp[k][0], k01.x);
            d2 = fma2(qp[k][1], k01.y, d2);
            d2 = fma2(qp[k][2], k23.x, d2);
            d2 = fma2(qp[k][3], k23.y, d2);
            float lo, hi; upk2(d2, lo, hi);
            float e = __expf(lo + hi);
            l += e;
            u64 e2 = pk2(e, e);
            ulonglong2 v01 = kj[2], v23 = kj[3];
            a01 = fma2(e2, v01.x, a01);
            a23 = fma2(e2, v01.y, a23);
            a45 = fma2(e2, v23.x, a45);
            a67 = fma2(e2, v23.y, a67);
        }
        u64 yp[4];
        {
            float inv_l = 1.f / l;
            float acc[8];
            upk2(a01, acc[0], acc[1]); upk2(a23, acc[2], acc[3]);
            upk2(a45, acc[4], acc[5]); upk2(a67, acc[6], acc[7]);
            #pragma unroll
            for (int i = 0; i < 4; i++)
                yp[i] = pk2(tf32r(acc[2*i] * inv_l), tf32r(acc[2*i+1] * inv_l));
        }

        float xa[8];
        #pragma unroll
        for (int o = 0; o < 8; o++) xa[o] = xr[k][o] + dot8p(yp, s_projT[o]);

        u64 h2p[4];
        ln_pack(xa, s_ln[2], s_ln[3], h2p);

        u64 o01 = 0, o23 = 0, o45 = 0, o67 = 0;
        #pragma unroll
        for (int f = 0; f < FFD; f++) {
            float z = dot8p(h2p, s_W1c[f]);
            z = tf32r(0.5f * z * (1.f + erff(z * 0.7071067811865475f)));
            u64 z2 = pk2(z, z);
            const ulonglong2* W2 = (const ulonglong2*)s_W2c[f];
            ulonglong2 w01 = W2[0], w23 = W2[1];
            o01 = fma2(z2, w01.x, o01);
            o23 = fma2(z2, w01.y, o23);
            o45 = fma2(z2, w23.x, o45);
            o67 = fma2(z2, w23.y, o67);
        }
        float o8[8];
        upk2(o01, o8[0], o8[1]); upk2(o23, o8[2], o8[3]);
        upk2(o45, o8[4], o8[5]); upk2(o67, o8[6], o8[7]);

        *(float4*)(gout + base)     = make_float4(xa[0]+o8[0], xa[1]+o8[1], xa[2]+o8[2], xa[3]+o8[3]);
        *(float4*)(gout + base + 4) = make_float4(xa[4]+o8[4], xa[5]+o8[5], xa[6]+o8[6], xa[7]+o8[7]);
    }

    // ====== Phase C: token 32 (warp 0 only; its KV is read only by itself,
    //        and its own writes are same-thread => no extra barrier needed) ======
    if (w == 0) {
        const int t = TT - 1;  // 32
        const long base = seqbase + (long)t * DM;
        float xc[8];
        {
            float4 a0 = *(const float4*)(gx + base);
            float4 a1 = *(const float4*)(gx + base + 4);
            xc[0]=a0.x; xc[1]=a0.y; xc[2]=a0.z; xc[3]=a0.w;
            xc[4]=a1.x; xc[5]=a1.y; xc[6]=a1.z; xc[7]=a1.w;
        }
        u64 hp[4];
        ln_pack(xc, s_ln[0], s_ln[1], hp);
        u64 qc[4];
        {
            float q[8];
            #pragma unroll
            for (int o = 0; o < 8; o++) q[o] = tf32r(dot8p(hp, s_qkvT[o])) * qscale;
            #pragma unroll
            for (int i = 0; i < 4; i++) qc[i] = pk2(q[2*i], q[2*i+1]);
            float kvv[16];
            #pragma unroll
            for (int o = 0; o < 16; o++) kvv[o] = tf32r(dot8p(hp, s_qkvT[8 + o]));
            float* dst = s_kv + s*KVSTRIDE + t*16;
            #pragma unroll
            for (int i = 0; i < 4; i++)
                ((float4*)dst)[i] = make_float4(kvv[4*i], kvv[4*i+1], kvv[4*i+2], kvv[4*i+3]);
        }

        u64 a01 = 0, a23 = 0, a45 = 0, a67 = 0;
        float l = 0.f;
        const float* kvp = s_kv + s*KVSTRIDE;
        for (int j = 0; j <= t; j++) {
            const ulonglong2* kj = (const ulonglong2*)(kvp + j*16);
            ulonglong2 k01 = kj[0], k23 = kj[1];
            u64 d2 = mul2(qc[0], k01.x);
            d2 = fma2(qc[1], k01.y, d2);
            d2 = fma2(qc[2], k23.x, d2);
            d2 = fma2(qc[3], k23.y, d2);
            float lo, hi; upk2(d2, lo, hi);
            float e = __expf(lo + hi);
            l += e;
            u64 e2 = pk2(e, e);
            ulonglong2 v01 = kj[2], v23 = kj[3];
            a01 = fma2(e2, v01.x, a01);
            a23 = fma2(e2, v01.y, a23);
            a45 = fma2(e2, v23.x, a45);
            a67 = fma2(e2, v23.y, a67);
        }
        u64 yp[4];
        {
            float inv_l = 1.f / l;
            float acc[8];
            upk2(a01, acc[0], acc[1]); upk2(a23, acc[2], acc[3]);
            upk2(a45, acc[4], acc[5]); upk2(a67, acc[6], acc[7]);
            #pragma unroll
            for (int i = 0; i < 4; i++)
                yp[i] = pk2(tf32r(acc[2*i] * inv_l), tf32r(acc[2*i+1] * inv_l));
        }
        float xa[8];
        #pragma unroll
        for (int o = 0; o < 8; o++) xa[o] = xc[o] + dot8p(yp, s_projT[o]);
        u64 h2p[4];
        ln_pack(xa, s_ln[2], s_ln[3], h2p);
        u64 o01 = 0, o23 = 0, o45 = 0, o67 = 0;
        #pragma unroll
        for (int f = 0; f < FFD; f++) {
            float z = dot8p(h2p, s_W1c[f]);
            z = tf32r(0.5f * z * (1.f + erff(z * 0.7071067811865475f)));
            u64 z2 = pk2(z, z);
            const ulonglong2* W2 = (const ulonglong2*)s_W2c[f];
            ulonglong2 w01 = W2[0], w23 = W2[1];
            o01 = fma2(z2, w01.x, o01);
            o23 = fma2(z2, w01.y, o23);
            o45 = fma2(z2, w23.x, o45);
            o67 = fma2(z2, w23.y, o67);
        }
        float o8[8];
        upk2(o01, o8[0], o8[1]); upk2(o23, o8[2], o8[3]);
        upk2(o45, o8[4], o8[5]); upk2(o67, o8[6], o8[7]);
        *(float4*)(gout + base)     = make_float4(xa[0]+o8[0], xa[1]+o8[1], xa[2]+o8[2], xa[3]+o8[3]);
        *(float4*)(gout + base + 4) = make_float4(xa[4]+o8[4], xa[5]+o8[5], xa[6]+o8[6], xa[7]+o8[7]);
    }
}

extern "C" void kernel_launch(void* const* d_in, const int* in_sizes, int n_in,
                              void* d_out, int out_size) {
    const float* x     = (const float*)d_in[0];
    const float* ln1w  = (const float*)d_in[1];
    const float* ln1b  = (const float*)d_in[2];
    const float* qkvw  = (const float*)d_in[3];
    const float* projw = (const float*)d_in[4];
    const float* ln2w  = (const float*)d_in[5];
    const float* ln2b  = (const float*)d_in[6];
    const float* f1A   = (const float*)d_in[7];
    const float* f1B   = (const float*)d_in[8];
    const float* f1W   = (const float*)d_in[9];
    const float* f2A   = (const float*)d_in[10];
    const float* f2B   = (const float*)d_in[11];
    const float* f2W   = (const float*)d_in[12];
    float* out = (float*)d_out;

    // Raise the dynamic-smem cap (host attribute set, not a stream op; capture-safe)
    cudaFuncSetAttribute(block_fused_kernel,
                         cudaFuncAttributeMaxDynamicSharedMemorySize, KVBYTES);

    block_fused_kernel<<<NBLOCKS, NTHREADS, KVBYTES>>>(
        x, ln1w, ln1b, qkvw, projw, ln2w, ln2b,
        f1A, f1B, f1W, f2A, f2B, f2W, out);
}

// round 9
// speedup vs baseline: 3.7586x; 3.7586x over previous
#include <cuda_runtime.h>
#include <cstdint>

// Problem constants (fixed by the reference config)
#define DM 8       // d_model
#define TT 33      // seq_len
#define FFD 28     // d_ff
#define RR 3       // ffn_rank
#define NMODELS 8
#define NBATCH 4096

#define NSEQ 16                         // sequences per block (2 per thread)
#define NTHREADS (TT * NSEQ / 2)        // 264 threads, 2 tokens each
#define BLOCKS_PER_MODEL (NBATCH / NSEQ)   // 256
#define NBLOCKS (NMODELS * BLOCKS_PER_MODEL) // 2048

// KV row stride (floats) per sequence-pair: 33 tokens * 32 floats + 4 pad.
// 1060 mod 32 = 4 => sp*4 gives 8 distinct bank quads; each LDS.128 access
// (8 unique addresses, 4-way broadcast across t-groups) covers all 32 banks.
#define KVSTRIDE (TT*32 + 4)

typedef unsigned long long u64;

// ---- TF32 rounding (matches reference's TF32 tensor-core einsums) ----
__device__ __forceinline__ float tf32r(float x) {
    uint32_t y;
    asm("cvt.rna.tf32.f32 %0, %1;" : "=r"(y) : "f"(x));
    return __uint_as_float(y);
}

// ---- packed f32x2 ops (sm_100+): one instruction, two FMAs ----
__device__ __forceinline__ u64 pk2(float lo, float hi) {
    u64 r; asm("mov.b64 %0, {%1, %2};" : "=l"(r) : "f"(lo), "f"(hi)); return r;
}
__device__ __forceinline__ void upk2(u64 v, float& lo, float& hi) {
    asm("mov.b64 {%0, %1}, %2;" : "=f"(lo), "=f"(hi) : "l"(v));
}
__device__ __forceinline__ u64 fma2(u64 a, u64 b, u64 c) {
    u64 d; asm("fma.rn.f32x2 %0, %1, %2, %3;" : "=l"(d) : "l"(a), "l"(b), "l"(c)); return d;
}
__device__ __forceinline__ u64 mul2(u64 a, u64 b) {
    u64 d; asm("mul.rn.f32x2 %0, %1, %2;" : "=l"(d) : "l"(a), "l"(b)); return d;
}

__device__ __forceinline__ float dot8w(const u64* a, u64 w0, u64 w1, u64 w2, u64 w3) {
    u64 acc = mul2(a[0], w0);
    acc = fma2(a[1], w1, acc);
    acc = fma2(a[2], w2, acc);
    acc = fma2(a[3], w3, acc);
    float lo, hi; upk2(acc, lo, hi);
    return lo + hi;
}

__global__ __launch_bounds__(NTHREADS, 3)   // target 3 blocks/SM (~82 regs)
void block_fused_kernel(
    const float* __restrict__ gx,
    const float* __restrict__ gln1w, const float* __restrict__ gln1b,
    const float* __restrict__ gqkv,  const float* __restrict__ gproj,
    const float* __restrict__ gln2w, const float* __restrict__ gln2b,
    const float* __restrict__ gf1A,  const float* __restrict__ gf1B,
    const float* __restrict__ gf1W,  const float* __restrict__ gf2A,
    const float* __restrict__ gf2B,  const float* __restrict__ gf2W,
    float* __restrict__ gout)
{
    __shared__ __align__(16) float s_qkvT[3*DM][DM];   // [o][i]
    __shared__ __align__(16) float s_projT[DM][DM];    // [o][i]
    __shared__ __align__(16) float s_W1c[FFD][DM];     // [f][i] = f1Wf + f1A@f1B
    __shared__ __align__(16) float s_W2c[FFD][DM];     // [f][d] = f2Wf + f2A@f2B
    __shared__ __align__(16) float s_ln[4][DM];        // ln1w, ln1b, ln2w, ln2b
    // per (spair, token): [k_a(8) | k_b(8) | v_a(8) | v_b(8)]
    __shared__ __align__(16) float s_kv[NSEQ/2][KVSTRIDE];

    const int tid = threadIdx.x;
    const int m  = blockIdx.x / BLOCKS_PER_MODEL;
    const int b0 = (blockIdx.x % BLOCKS_PER_MODEL) * NSEQ;

    // ---- stage weights (TF32-rounded; transposed; low-rank terms folded) ----
    for (int idx = tid; idx < 3*DM*DM; idx += NTHREADS) {
        int o = idx / DM, i = idx % DM;
        s_qkvT[o][i] = tf32r(gqkv[((long)m*DM + i)*(3*DM) + o]);
    }
    for (int idx = tid; idx < DM*DM; idx += NTHREADS) {
        int o = idx / DM, i = idx % DM;
        s_projT[o][i] = tf32r(gproj[((long)m*DM + i)*DM + o]);
    }
    for (int idx = tid; idx < FFD*DM; idx += NTHREADS) {
        int f = idx / DM, i = idx % DM;
        float acc = gf1W[((long)m*DM + i)*FFD + f];
        #pragma unroll
        for (int r = 0; r < RR; r++)
            acc = fmaf(gf1A[((long)m*DM + i)*RR + r],
                       gf1B[((long)m*RR + r)*FFD + f], acc);
        s_W1c[f][i] = tf32r(acc);
    }
    for (int idx = tid; idx < FFD*DM; idx += NTHREADS) {
        int f = idx / DM, d = idx % DM;
        float acc = gf2W[((long)m*FFD + f)*DM + d];
        #pragma unroll
        for (int r = 0; r < RR; r++)
            acc = fmaf(gf2A[((long)m*FFD + f)*RR + r],
                       gf2B[((long)m*RR + r)*DM + d], acc);
        s_W2c[f][d] = tf32r(acc);
    }
    for (int idx = tid; idx < 4*DM; idx += NTHREADS) {
        int which = idx / DM, i = idx % DM;
        const float* src = (which == 0) ? gln1w : (which == 1) ? gln1b
                         : (which == 2) ? gln2w : gln2b;
        s_ln[which][i] = src[(long)m*DM + i];
    }

    __syncthreads();  // staging visible before any weight reads

    // ---- two tokens per thread: (sp, t) and (sp+8, t) ----
    const int sp = tid & 7;   // sequence-pair index
    const int t  = tid >> 3;  // token index (warps span 4 consecutive t)
    const long baseA = ((((long)m*NBATCH + b0 + sp    )*TT) + t) * DM;
    const long baseB = ((((long)m*NBATCH + b0 + sp + 8)*TT) + t) * DM;

    // LN1 + QKV. x is NOT kept live (register diet) — reloaded at proj time.
    u64 qp[2][4];
    {
        float kvv[2][16];
        u64 hp[2][4];
        #pragma unroll
        for (int k = 0; k < 2; k++) {
            const long base = k ? baseB : baseA;
            float4 a0 = *(const float4*)(gx + base);
            float4 a1 = *(const float4*)(gx + base + 4);
            float xv[8] = {a0.x,a0.y,a0.z,a0.w,a1.x,a1.y,a1.z,a1.w};
            float mean = 0.f;
            #pragma unroll
            for (int i = 0; i < 8; i++) mean += xv[i];
            mean *= 0.125f;
            float var = 0.f;
            #pragma unroll
            for (int i = 0; i < 8; i++) { float d = xv[i] - mean; var += d*d; }
            var *= 0.125f;
            float rstd = rsqrtf(var + 1e-5f);
            float h[8];
            #pragma unroll
            for (int i = 0; i < 8; i++)
                h[i] = tf32r((xv[i] - mean) * rstd * s_ln[0][i] + s_ln[1][i]);
            #pragma unroll
            for (int i = 0; i < 4; i++) hp[k][i] = pk2(h[2*i], h[2*i+1]);
        }

        const float qscale = 0.3535533905932738f;  // 1/sqrt(8)
        float q[2][8];
        #pragma unroll
        for (int o = 0; o < 8; o++) {
            const ulonglong2* W = (const ulonglong2*)s_qkvT[o];
            ulonglong2 w01 = W[0], w23 = W[1];
            q[0][o] = tf32r(dot8w(hp[0], w01.x, w01.y, w23.x, w23.y)) * qscale;
            q[1][o] = tf32r(dot8w(hp[1], w01.x, w01.y, w23.x, w23.y)) * qscale;
        }
        #pragma unroll
        for (int o = 0; o < 16; o++) {
            const ulonglong2* W = (const ulonglong2*)s_qkvT[8 + o];
            ulonglong2 w01 = W[0], w23 = W[1];
            kvv[0][o] = tf32r(dot8w(hp[0], w01.x, w01.y, w23.x, w23.y));
            kvv[1][o] = tf32r(dot8w(hp[1], w01.x, w01.y, w23.x, w23.y));
        }
        #pragma unroll
        for (int k = 0; k < 2; k++)
            #pragma unroll
            for (int i = 0; i < 4; i++) qp[k][i] = pk2(q[k][2*i], q[k][2*i+1]);

        // layout per token: [k_a | k_b | v_a | v_b]
        float* dst = &s_kv[sp][t*32];
        #pragma unroll
        for (int i = 0; i < 2; i++) {
            ((float4*)dst)[i]     = make_float4(kvv[0][4*i], kvv[0][4*i+1], kvv[0][4*i+2], kvv[0][4*i+3]);
            ((float4*)dst)[2 + i] = make_float4(kvv[1][4*i], kvv[1][4*i+1], kvv[1][4*i+2], kvv[1][4*i+3]);
            ((float4*)dst)[4 + i] = make_float4(kvv[0][8+4*i], kvv[0][9+4*i], kvv[0][10+4*i], kvv[0][11+4*i]);
            ((float4*)dst)[6 + i] = make_float4(kvv[1][8+4*i], kvv[1][9+4*i], kvv[1][10+4*i], kvv[1][11+4*i]);
        }
    }
    __syncthreads();

    // Single-pass causal attention for both sequences (scores tiny => no max).
    u64 acc[2][4] = {{0,0,0,0},{0,0,0,0}};
    float l[2] = {0.f, 0.f};
    {
        const float* kvp = &s_kv[sp][0];
        for (int j = 0; j <= t; j++) {
            const ulonglong2* row = (const ulonglong2*)(kvp + j*32);
            ulonglong2 ka = row[0], kb = row[1];   // k_a[0..7]
            ulonglong2 kc = row[2], kd = row[3];   // k_b[0..7]
            float ea, eb;
            {
                u64 d2 = mul2(qp[0][0], ka.x);
                d2 = fma2(qp[0][1], ka.y, d2);
                d2 = fma2(qp[0][2], kb.x, d2);
                d2 = fma2(qp[0][3], kb.y, d2);
                float lo, hi; upk2(d2, lo, hi);
                ea = __expf(lo + hi);
            }
            {
                u64 d2 = mul2(qp[1][0], kc.x);
                d2 = fma2(qp[1][1], kc.y, d2);
                d2 = fma2(qp[1][2], kd.x, d2);
                d2 = fma2(qp[1][3], kd.y, d2);
                float lo, hi; upk2(d2, lo, hi);
                eb = __expf(lo + hi);
            }
            l[0] += ea;  l[1] += eb;
            u64 e2a = pk2(ea, ea), e2b = pk2(eb, eb);
            ulonglong2 va = row[4], vb = row[5];   // v_a
            ulonglong2 vc = row[6], vd = row[7];   // v_b
            acc[0][0] = fma2(e2a, va.x, acc[0][0]);
            acc[0][1] = fma2(e2a, va.y, acc[0][1]);
            acc[0][2] = fma2(e2a, vb.x, acc[0][2]);
            acc[0][3] = fma2(e2a, vb.y, acc[0][3]);
            acc[1][0] = fma2(e2b, vc.x, acc[1][0]);
            acc[1][1] = fma2(e2b, vc.y, acc[1][1]);
            acc[1][2] = fma2(e2b, vd.x, acc[1][2]);
            acc[1][3] = fma2(e2b, vd.y, acc[1][3]);
        }
    }
    u64 yp[2][4];
    #pragma unroll
    for (int k = 0; k < 2; k++) {
        float inv_l = 1.f / l[k];
        #pragma unroll
        for (int i = 0; i < 4; i++) {
            float lo, hi; upk2(acc[k][i], lo, hi);
            yp[k][i] = pk2(tf32r(lo * inv_l), tf32r(hi * inv_l));
        }
    }

    // proj + residual (x reloaded from gmem — likely L1-hot, saves 16 regs),
    // then LN2, packed
    float xa[2][8];
    u64 h2p[2][4];
    #pragma unroll
    for (int k = 0; k < 2; k++) {
        const long base = k ? baseB : baseA;
        float4 a0 = *(const float4*)(gx + base);
        float4 a1 = *(const float4*)(gx + base + 4);
        float xv[8] = {a0.x,a0.y,a0.z,a0.w,a1.x,a1.y,a1.z,a1.w};
        #pragma unroll
        for (int o = 0; o < 8; o++) {
            const ulonglong2* W = (const ulonglong2*)s_projT[o];
            ulonglong2 w01 = W[0], w23 = W[1];
            xa[k][o] = xv[o] + dot8w(yp[k], w01.x, w01.y, w23.x, w23.y);
        }
        float mean = 0.f;
        #pragma unroll
        for (int i = 0; i < 8; i++) mean += xa[k][i];
        mean *= 0.125f;
        float var = 0.f;
        #pragma unroll
        for (int i = 0; i < 8; i++) { float d = xa[k][i] - mean; var += d*d; }
        var *= 0.125f;
        float rstd = rsqrtf(var + 1e-5f);
        float h2[8];
        #pragma unroll
        for (int i = 0; i < 8; i++)
            h2[i] = tf32r((xa[k][i] - mean) * rstd * s_ln[2][i] + s_ln[3][i]);
        #pragma unroll
        for (int i = 0; i < 4; i++) h2p[k][i] = pk2(h2[2*i], h2[2*i+1]);
    }

    // MLP with combined weights, rows shared across the two tokens
    u64 o2[2][4] = {{0,0,0,0},{0,0,0,0}};
    #pragma unroll
    for (int f = 0; f < FFD; f++) {
        const ulonglong2* W1 = (const ulonglong2*)s_W1c[f];
        ulonglong2 u01 = W1[0], u23 = W1[1];
        float za = dot8w(h2p[0], u01.x, u01.y, u23.x, u23.y);
        float zb = dot8w(h2p[1], u01.x, u01.y, u23.x, u23.y);
        za = tf32r(0.5f * za * (1.f + erff(za * 0.7071067811865475f)));
        zb = tf32r(0.5f * zb * (1.f + erff(zb * 0.7071067811865475f)));
        u64 z2a = pk2(za, za), z2b = pk2(zb, zb);
        const ulonglong2* W2 = (const ulonglong2*)s_W2c[f];
        ulonglong2 w01 = W2[0], w23 = W2[1];
        o2[0][0] = fma2(z2a, w01.x, o2[0][0]);
        o2[0][1] = fma2(z2a, w01.y, o2[0][1]);
        o2[0][2] = fma2(z2a, w23.x, o2[0][2]);
        o2[0][3] = fma2(z2a, w23.y, o2[0][3]);
        o2[1][0] = fma2(z2b, w01.x, o2[1][0]);
        o2[1][1] = fma2(z2b, w01.y, o2[1][1]);
        o2[1][2] = fma2(z2b, w23.x, o2[1][2]);
        o2[1][3] = fma2(z2b, w23.y, o2[1][3]);
    }

    #pragma unroll
    for (int k = 0; k < 2; k++) {
        float o8[8];
        upk2(o2[k][0], o8[0], o8[1]); upk2(o2[k][1], o8[2], o8[3]);
        upk2(o2[k][2], o8[4], o8[5]); upk2(o2[k][3], o8[6], o8[7]);
        long base = k ? baseB : baseA;
        *(float4*)(gout + base)     = make_float4(xa[k][0]+o8[0], xa[k][1]+o8[1], xa[k][2]+o8[2], xa[k][3]+o8[3]);
        *(float4*)(gout + base + 4) = make_float4(xa[k][4]+o8[4], xa[k][5]+o8[5], xa[k][6]+o8[6], xa[k][7]+o8[7]);
    }
}

extern "C" void kernel_launch(void* const* d_in, const int* in_sizes, int n_in,
                              void* d_out, int out_size) {
    const float* x     = (const float*)d_in[0];
    const float* ln1w  = (const float*)d_in[1];
    const float* ln1b  = (const float*)d_in[2];
    const float* qkvw  = (const float*)d_in[3];
    const float* projw = (const float*)d_in[4];
    const float* ln2w  = (const float*)d_in[5];
    const float* ln2b  = (const float*)d_in[6];
    const float* f1A   = (const float*)d_in[7];
    const float* f1B   = (const float*)d_in[8];
    const float* f1W   = (const float*)d_in[9];
    const float* f2A   = (const float*)d_in[10];
    const float* f2B   = (const float*)d_in[11];
    const float* f2W   = (const float*)d_in[12];
    float* out = (float*)d_out;

    block_fused_kernel<<<NBLOCKS, NTHREADS>>>(
        x, ln1w, ln1b, qkvw, projw, ln2w, ln2b,
        f1A, f1B, f1W, f2A, f2B, f2W, out);
}

// round 10
// speedup vs baseline: 4.2428x; 1.1288x over previous
#include <cuda_runtime.h>
#include <cstdint>

// Problem constants (fixed by the reference config)
#define DM 8       // d_model
#define TT 33      // seq_len
#define FFD 28     // d_ff
#define RR 3       // ffn_rank
#define NMODELS 8
#define NBATCH 4096

#define NSEQ 8                    // sequences per block
#define NTHREADS (TT * NSEQ)      // 264 threads
#define BLOCKS_PER_MODEL (NBATCH / NSEQ)   // 512
#define NBLOCKS (NMODELS * BLOCKS_PER_MODEL)

// Per-sequence KV row stride in floats: TT*16 + 4 = 532 (conflict-free octet
// access under the s-fast lane mapping; verified in R5/R6).
#define KVSTRIDE (TT*16 + 4)

typedef unsigned long long u64;

// ---- TF32 rounding (matches reference's TF32 tensor-core einsums) ----
__device__ __forceinline__ float tf32r(float x) {
    uint32_t y;
    asm("cvt.rna.tf32.f32 %0, %1;" : "=r"(y) : "f"(x));
    return __uint_as_float(y);
}

// ---- packed f32x2 ops (sm_100+): one instruction, two FMAs ----
__device__ __forceinline__ u64 pk2(float lo, float hi) {
    u64 r; asm("mov.b64 %0, {%1, %2};" : "=l"(r) : "f"(lo), "f"(hi)); return r;
}
__device__ __forceinline__ void upk2(u64 v, float& lo, float& hi) {
    asm("mov.b64 {%0, %1}, %2;" : "=f"(lo), "=f"(hi) : "l"(v));
}
__device__ __forceinline__ u64 fma2(u64 a, u64 b, u64 c) {
    u64 d; asm("fma.rn.f32x2 %0, %1, %2, %3;" : "=l"(d) : "l"(a), "l"(b), "l"(c)); return d;
}
__device__ __forceinline__ u64 mul2(u64 a, u64 b) {
    u64 d; asm("mul.rn.f32x2 %0, %1, %2;" : "=l"(d) : "l"(a), "l"(b)); return d;
}

__device__ __forceinline__ float dot8p(const u64* a, const float* w) {
    const ulonglong2* W = (const ulonglong2*)w;
    ulonglong2 w01 = W[0], w23 = W[1];
    u64 acc = mul2(a[0], w01.x);
    acc = fma2(a[1], w01.y, acc);
    acc = fma2(a[2], w23.x, acc);
    acc = fma2(a[3], w23.y, acc);
    float lo, hi; upk2(acc, lo, hi);
    return lo + hi;
}

// Exact-erf GELU via Abramowitz-Stegun 7.1.26 (|eps| <= 1.5e-7 abs),
// branchless: 1 MUFU.RCP + 5 FMA + 1 MUFU.EX2 + sign ops. Far cheaper than
// libdevice erff (branchy multi-poly) at accuracy 1000x below our budget.
__device__ __forceinline__ float gelu_ex(float z) {
    float x = z * 0.7071067811865475f;
    float ax = fabsf(x);
    float den = fmaf(0.3275911f, ax, 1.0f);
    float t;
    asm("rcp.approx.f32 %0, %1;" : "=f"(t) : "f"(den));
    float p = fmaf(t, 1.061405429f, -1.453152027f);
    p = fmaf(t, p, 1.421413741f);
    p = fmaf(t, p, -0.284496736f);
    p = fmaf(t, p, 0.254829592f);
    p = p * t;
    float e = __expf(-x * x);
    float erfa = fmaf(-p, e, 1.0f);          // erf(|x|)
    float erfv = copysignf(erfa, z);
    return 0.5f * z * (1.0f + erfv);
}

__global__ __launch_bounds__(NTHREADS, 4)   // 4 blocks/SM target (~62 regs)
void block_fused_kernel(
    const float* __restrict__ gx,
    const float* __restrict__ gln1w, const float* __restrict__ gln1b,
    const float* __restrict__ gqkv,  const float* __restrict__ gproj,
    const float* __restrict__ gln2w, const float* __restrict__ gln2b,
    const float* __restrict__ gf1A,  const float* __restrict__ gf1B,
    const float* __restrict__ gf1W,  const float* __restrict__ gf2A,
    const float* __restrict__ gf2B,  const float* __restrict__ gf2W,
    float* __restrict__ gout)
{
    __shared__ __align__(16) float s_qkvT[3*DM][DM];   // [o][i]
    __shared__ __align__(16) float s_projT[DM][DM];    // [o][i]
    __shared__ __align__(16) float s_W1c[FFD][DM];     // [f][i] = f1Wf + f1A@f1B
    __shared__ __align__(16) float s_W2c[FFD][DM];     // [f][d] = f2Wf + f2A@f2B
    __shared__ __align__(16) float s_ln[4][DM];        // ln1w, ln1b, ln2w, ln2b
    __shared__ __align__(16) float s_kv[NSEQ][KVSTRIDE]; // per token: K(8) | V(8)

    const int tid = threadIdx.x;
    const int m  = blockIdx.x / BLOCKS_PER_MODEL;
    const int b0 = (blockIdx.x % BLOCKS_PER_MODEL) * NSEQ;

    // ---- stage weights (TF32-rounded; transposed; low-rank terms folded) ----
    for (int idx = tid; idx < 3*DM*DM; idx += NTHREADS) {
        int o = idx / DM, i = idx % DM;
        s_qkvT[o][i] = tf32r(gqkv[((long)m*DM + i)*(3*DM) + o]);
    }
    for (int idx = tid; idx < DM*DM; idx += NTHREADS) {
        int o = idx / DM, i = idx % DM;
        s_projT[o][i] = tf32r(gproj[((long)m*DM + i)*DM + o]);
    }
    for (int idx = tid; idx < FFD*DM; idx += NTHREADS) {
        int f = idx / DM, i = idx % DM;
        float acc = gf1W[((long)m*DM + i)*FFD + f];
        #pragma unroll
        for (int r = 0; r < RR; r++)
            acc = fmaf(gf1A[((long)m*DM + i)*RR + r],
                       gf1B[((long)m*RR + r)*FFD + f], acc);
        s_W1c[f][i] = tf32r(acc);
    }
    for (int idx = tid; idx < FFD*DM; idx += NTHREADS) {
        int f = idx / DM, d = idx % DM;
        float acc = gf2W[((long)m*FFD + f)*DM + d];
        #pragma unroll
        for (int r = 0; r < RR; r++)
            acc = fmaf(gf2A[((long)m*FFD + f)*RR + r],
                       gf2B[((long)m*RR + r)*DM + d], acc);
        s_W2c[f][d] = tf32r(acc);
    }
    for (int idx = tid; idx < 4*DM; idx += NTHREADS) {
        int which = idx / DM, i = idx % DM;
        const float* src = (which == 0) ? gln1w : (which == 1) ? gln1b
                         : (which == 2) ? gln2w : gln2b;
        s_ln[which][i] = src[(long)m*DM + i];
    }

    __syncthreads();  // staging visible before any weight reads

    // ---- per-token pipeline (s fast, t slow: minimal warp divergence) ----
    const int s = tid & 7;
    const int t = tid >> 3;
    const long base = ((((long)m*NBATCH + b0 + s)*TT) + t) * DM;

    float4 x0 = *(const float4*)(gx + base);
    float4 x1 = *(const float4*)(gx + base + 4);
    float xr[8] = {x0.x, x0.y, x0.z, x0.w, x1.x, x1.y, x1.z, x1.w};

    // LN1 (exact fp32), output TF32-quantized for the qkv einsum
    u64 hp[4];
    {
        float mean = 0.f;
        #pragma unroll
        for (int i = 0; i < 8; i++) mean += xr[i];
        mean *= 0.125f;
        float var = 0.f;
        #pragma unroll
        for (int i = 0; i < 8; i++) { float d = xr[i] - mean; var += d*d; }
        var *= 0.125f;
        float rstd = rsqrtf(var + 1e-5f);
        float h[8];
        #pragma unroll
        for (int i = 0; i < 8; i++)
            h[i] = tf32r((xr[i] - mean) * rstd * s_ln[0][i] + s_ln[1][i]);
        #pragma unroll
        for (int i = 0; i < 4; i++) hp[i] = pk2(h[2*i], h[2*i+1]);
    }

    const float qscale = 0.3535533905932738f;  // 1/sqrt(8)

    // QKV (operands TF32); q pre-scaled after quantization, kept packed
    u64 qp[4];
    {
        float q[8];
        #pragma unroll
        for (int o = 0; o < 8; o++) q[o] = tf32r(dot8p(hp, s_qkvT[o])) * qscale;
        #pragma unroll
        for (int i = 0; i < 4; i++) qp[i] = pk2(q[2*i], q[2*i+1]);

        float kvv[16];
        #pragma unroll
        for (int o = 0; o < 8; o++) kvv[o]     = tf32r(dot8p(hp, s_qkvT[8 + o]));
        #pragma unroll
        for (int o = 0; o < 8; o++) kvv[8 + o] = tf32r(dot8p(hp, s_qkvT[16 + o]));
        float* dst = &s_kv[s][t*16];
        #pragma unroll
        for (int i = 0; i < 4; i++)
            ((float4*)dst)[i] = make_float4(kvv[4*i], kvv[4*i+1], kvv[4*i+2], kvv[4*i+3]);
    }
    __syncthreads();

    // Single-pass causal attention (scores tiny => no max subtraction),
    // packed accumulators: 4 dual-FMAs per V row.
    u64 a01 = 0, a23 = 0, a45 = 0, a67 = 0;
    float l = 0.f;
    {
        const float* kvp = &s_kv[s][0];
        for (int j = 0; j <= t; j++) {
            const ulonglong2* kj = (const ulonglong2*)(kvp + j*16);
            ulonglong2 k01 = kj[0], k23 = kj[1];
            u64 d2 = mul2(qp[0], k01.x);
            d2 = fma2(qp[1], k01.y, d2);
            d2 = fma2(qp[2], k23.x, d2);
            d2 = fma2(qp[3], k23.y, d2);
            float lo, hi; upk2(d2, lo, hi);
            float e = __expf(lo + hi);
            l += e;
            u64 e2 = pk2(e, e);
            ulonglong2 v01 = kj[2], v23 = kj[3];
            a01 = fma2(e2, v01.x, a01);
            a23 = fma2(e2, v01.y, a23);
            a45 = fma2(e2, v23.x, a45);
            a67 = fma2(e2, v23.y, a67);
        }
    }
    u64 yp[4];
    {
        float inv_l = 1.f / l;
        float acc[8];
        upk2(a01, acc[0], acc[1]); upk2(a23, acc[2], acc[3]);
        upk2(a45, acc[4], acc[5]); upk2(a67, acc[6], acc[7]);
        #pragma unroll
        for (int i = 0; i < 4; i++)
            yp[i] = pk2(tf32r(acc[2*i] * inv_l), tf32r(acc[2*i+1] * inv_l));
    }

    // proj + residual
    float xa[8];
    #pragma unroll
    for (int o = 0; o < 8; o++) xa[o] = xr[o] + dot8p(yp, s_projT[o]);

    // LN2
    u64 h2p[4];
    {
        float mean = 0.f;
        #pragma unroll
        for (int i = 0; i < 8; i++) mean += xa[i];
        mean *= 0.125f;
        float var = 0.f;
        #pragma unroll
        for (int i = 0; i < 8; i++) { float d = xa[i] - mean; var += d*d; }
        var *= 0.125f;
        float rstd = rsqrtf(var + 1e-5f);
        float h2[8];
        #pragma unroll
        for (int i = 0; i < 8; i++)
            h2[i] = tf32r((xa[i] - mean) * rstd * s_ln[2][i] + s_ln[3][i]);
        #pragma unroll
        for (int i = 0; i < 4; i++) h2p[i] = pk2(h2[2*i], h2[2*i+1]);
    }

    // MLP with combined weights: h1 = gelu(h2 @ W1c); out = xa + h1 @ W2c
    u64 o01 = 0, o23 = 0, o45 = 0, o67 = 0;
    #pragma unroll
    for (int f = 0; f < FFD; f++) {
        float z = dot8p(h2p, s_W1c[f]);
        z = tf32r(gelu_ex(z));
        u64 z2 = pk2(z, z);
        const ulonglong2* W2 = (const ulonglong2*)s_W2c[f];
        ulonglong2 w01 = W2[0], w23 = W2[1];
        o01 = fma2(z2, w01.x, o01);
        o23 = fma2(z2, w01.y, o23);
        o45 = fma2(z2, w23.x, o45);
        o67 = fma2(z2, w23.y, o67);
    }

    float o8[8];
    upk2(o01, o8[0], o8[1]); upk2(o23, o8[2], o8[3]);
    upk2(o45, o8[4], o8[5]); upk2(o67, o8[6], o8[7]);

    *(float4*)(gout + base)     = make_float4(xa[0]+o8[0], xa[1]+o8[1], xa[2]+o8[2], xa[3]+o8[3]);
    *(float4*)(gout + base + 4) = make_float4(xa[4]+o8[4], xa[5]+o8[5], xa[6]+o8[6], xa[7]+o8[7]);
}

extern "C" void kernel_launch(void* const* d_in, const int* in_sizes, int n_in,
                              void* d_out, int out_size) {
    const float* x     = (const float*)d_in[0];
    const float* ln1w  = (const float*)d_in[1];
    const float* ln1b  = (const float*)d_in[2];
    const float* qkvw  = (const float*)d_in[3];
    const float* projw = (const float*)d_in[4];
    const float* ln2w  = (const float*)d_in[5];
    const float* ln2b  = (const float*)d_in[6];
    const float* f1A   = (const float*)d_in[7];
    const float* f1B   = (const float*)d_in[8];
    const float* f1W   = (const float*)d_in[9];
    const float* f2A   = (const float*)d_in[10];
    const float* f2B   = (const float*)d_in[11];
    const float* f2W   = (const float*)d_in[12];
    float* out = (float*)d_out;

    block_fused_kernel<<<NBLOCKS, NTHREADS>>>(
        x, ln1w, ln1b, qkvw, projw, ln2w, ln2b,
        f1A, f1B, f1W, f2A, f2B, f2W, out);
}